// round 4
// baseline (speedup 1.0000x reference)
#include <cuda_runtime.h>
#include <cstdint>

#define N_NODES 100000
#define C1 128
#define C2 64

// ---------------- scratch (static device globals; no allocation) ----------------
__device__ float g_h1  [(size_t)N_NODES * C1];   // x@W1, then in-place relu output
__device__ float g_acc1[(size_t)N_NODES * C1];   // layer-1 neighbor accumulator
__device__ float g_h2  [(size_t)N_NODES * C2];   // h@W2
__device__ float g_acc2[(size_t)N_NODES * C2];   // layer-2 neighbor accumulator
__device__ float g_dinv[N_NODES];
__device__ int   g_deg [N_NODES];
__device__ int   g_is64;                          // 1 if edge_index is int64

// ---------------- edge dtype detection ----------------
// int64 values < 100000 => every high 32-bit word is 0.
// int32 => odd int32 positions are random values in [0,100000); P(all 1024 zero) ~ 0.
__global__ void detect_kernel(const int* __restrict__ ei) {
    if (blockIdx.x == 0 && threadIdx.x == 0) {
        int any = 0;
        for (int i = 0; i < 1024; i++) any |= ei[2 * i + 1];
        g_is64 = (any == 0) ? 1 : 0;
    }
}

__device__ __forceinline__ int load_idx(const void* ei, long long pos) {
    if (g_is64) return (int)((const long long*)ei)[pos];
    return ((const int*)ei)[pos];
}

// ---------------- degree + dinv ----------------
__global__ void deg_kernel(const void* __restrict__ ei, int E) {
    int t = blockIdx.x * blockDim.x + threadIdx.x;
    if (t >= E) return;
    int d = load_idx(ei, (long long)E + t);
    atomicAdd(&g_deg[d], 1);
}

__global__ void dinv_kernel() {
    int t = blockIdx.x * blockDim.x + threadIdx.x;
    if (t < N_NODES) g_dinv[t] = rsqrtf((float)g_deg[t] + 1.0f);
}

// ---------------- register-blocked SGEMM: C[M,N] = A[M,K] * B[K,N] ----------------
// BM=128, BK=8, TM=8, TN=8; BN=128 (256 thr) or BN=64 (128 thr). Only M needs guards.
template <int BM, int BN, int BK, int TM, int TN>
__global__ void sgemm(int M, int N, int K,
                      const float* __restrict__ A,
                      const float* __restrict__ B,
                      float* __restrict__ C) {
    const int numThreads = (BM / TM) * (BN / TN);
    const int cRow = blockIdx.y;
    const int cCol = blockIdx.x;

    __shared__ float As[BK][BM];   // transposed A tile
    __shared__ float Bs[BK][BN];

    const int threadCol = threadIdx.x % (BN / TN);
    const int threadRow = threadIdx.x / (BN / TN);

    A += (size_t)cRow * BM * K;
    B += cCol * BN;
    C += (size_t)cRow * BM * N + cCol * BN;
    const int rowBase = cRow * BM;

    const int innerRowA = threadIdx.x / (BK / 4);
    const int innerColA = threadIdx.x % (BK / 4);
    const int strideA   = numThreads / (BK / 4);
    const int innerRowB = threadIdx.x / (BN / 4);
    const int innerColB = threadIdx.x % (BN / 4);
    const int strideB   = numThreads / (BN / 4);

    float regM[TM], regN[TN];
    float acc[TM][TN];
    #pragma unroll
    for (int i = 0; i < TM; i++)
        #pragma unroll
        for (int j = 0; j < TN; j++) acc[i][j] = 0.f;

    for (int k0 = 0; k0 < K; k0 += BK) {
        #pragma unroll
        for (int r = innerRowA; r < BM; r += strideA) {
            float4 t = make_float4(0.f, 0.f, 0.f, 0.f);
            if (rowBase + r < M)
                t = *(const float4*)(A + (size_t)r * K + innerColA * 4);
            As[innerColA * 4 + 0][r] = t.x;
            As[innerColA * 4 + 1][r] = t.y;
            As[innerColA * 4 + 2][r] = t.z;
            As[innerColA * 4 + 3][r] = t.w;
        }
        #pragma unroll
        for (int r = innerRowB; r < BK; r += strideB) {
            float4 t = *(const float4*)(B + (size_t)r * N + innerColB * 4);
            *(float4*)(&Bs[r][innerColB * 4]) = t;
        }
        __syncthreads();
        A += BK;
        B += (size_t)BK * N;

        #pragma unroll
        for (int k = 0; k < BK; k++) {
            #pragma unroll
            for (int i = 0; i < TM; i++) regM[i] = As[k][threadRow * TM + i];
            #pragma unroll
            for (int j = 0; j < TN; j++) regN[j] = Bs[k][threadCol * TN + j];
            #pragma unroll
            for (int i = 0; i < TM; i++)
                #pragma unroll
                for (int j = 0; j < TN; j++) acc[i][j] += regM[i] * regN[j];
        }
        __syncthreads();
    }

    #pragma unroll
    for (int i = 0; i < TM; i++) {
        int r = threadRow * TM + i;
        if (rowBase + r >= M) continue;
        #pragma unroll
        for (int j = 0; j < TN; j += 4) {
            float4 t;
            t.x = acc[i][j + 0]; t.y = acc[i][j + 1];
            t.z = acc[i][j + 2]; t.w = acc[i][j + 3];
            *(float4*)(&C[(size_t)r * N + threadCol * TN + j]) = t;
        }
    }
}

// ---------------- edge scatter, layer 1 (128 channels) ----------------
// One warp per edge: 32 lanes x float4 = 512B coalesced gather, vector reduction store.
// Message carries only dinv[src]; dinv[dst] is applied once in the epilogue.
__global__ void scatter128(const float* __restrict__ h, const void* __restrict__ ei,
                           int E, float* __restrict__ acc) {
    long long gtid = (long long)blockIdx.x * blockDim.x + threadIdx.x;
    int e    = (int)(gtid >> 5);
    int lane = threadIdx.x & 31;
    if (e >= E) return;
    int s = load_idx(ei, e);
    int d = load_idx(ei, (long long)E + e);
    float norm = g_dinv[s];
    float4 v = __ldg((const float4*)(h + (size_t)s * C1) + lane);
    float* dst = acc + (size_t)d * C1 + lane * 4;
    asm volatile("red.global.add.v4.f32 [%0], {%1, %2, %3, %4};"
                 :: "l"(dst), "f"(v.x * norm), "f"(v.y * norm),
                    "f"(v.z * norm), "f"(v.w * norm) : "memory");
}

// ---------------- edge scatter, layer 2 (64 channels) ----------------
// Two edges per warp: 16 lanes x float4 each.
__global__ void scatter64(const float* __restrict__ h, const void* __restrict__ ei,
                          int E, float* __restrict__ acc) {
    long long gtid = (long long)blockIdx.x * blockDim.x + threadIdx.x;
    int warp = (int)(gtid >> 5);
    int lane = threadIdx.x & 31;
    int e    = warp * 2 + (lane >> 4);
    int sub  = lane & 15;
    if (e >= E) return;
    int s = load_idx(ei, e);
    int d = load_idx(ei, (long long)E + e);
    float norm = g_dinv[s];
    float4 v = __ldg((const float4*)(h + (size_t)s * C2) + sub);
    float* dst = acc + (size_t)d * C2 + sub * 4;
    asm volatile("red.global.add.v4.f32 [%0], {%1, %2, %3, %4};"
                 :: "l"(dst), "f"(v.x * norm), "f"(v.y * norm),
                    "f"(v.z * norm), "f"(v.w * norm) : "memory");
}

// ---------------- epilogues ----------------
// acc holds Σ_{s->node} h[s]*dinv[s].  Full term = dinv[node]*acc + dinv^2*h + b.
// layer 1 additionally applies relu, in place into g_h1.
__global__ void epi1_kernel(const float* __restrict__ b1) {
    int t = blockIdx.x * blockDim.x + threadIdx.x;   // over N_NODES * 32 float4s
    if (t >= N_NODES * (C1 / 4)) return;
    int node = t / (C1 / 4);
    int c4   = t % (C1 / 4);
    float di  = g_dinv[node];
    float di2 = di * di;
    float4 a = ((const float4*)g_acc1)[t];
    float4 h = ((const float4*)g_h1)[t];
    float4 b = ((const float4*)b1)[c4];
    float4 o;
    o.x = fmaxf(di * a.x + di2 * h.x + b.x, 0.f);
    o.y = fmaxf(di * a.y + di2 * h.y + b.y, 0.f);
    o.z = fmaxf(di * a.z + di2 * h.z + b.z, 0.f);
    o.w = fmaxf(di * a.w + di2 * h.w + b.w, 0.f);
    ((float4*)g_h1)[t] = o;
}

// layer 2: out <- dinv*acc2 + dinv^2*h2 + b2
__global__ void epi2_kernel(const float* __restrict__ b2, float* __restrict__ out) {
    int t = blockIdx.x * blockDim.x + threadIdx.x;   // over N_NODES * 16 float4s
    if (t >= N_NODES * (C2 / 4)) return;
    int node = t / (C2 / 4);
    int c4   = t % (C2 / 4);
    float di  = g_dinv[node];
    float di2 = di * di;
    float4 a = ((const float4*)g_acc2)[t];
    float4 h = ((const float4*)g_h2)[t];
    float4 b = ((const float4*)b2)[c4];
    float4 o;
    o.x = di * a.x + di2 * h.x + b.x;
    o.y = di * a.y + di2 * h.y + b.y;
    o.z = di * a.z + di2 * h.z + b.z;
    o.w = di * a.w + di2 * h.w + b.w;
    ((float4*)out)[t] = o;
}

// ---------------- launch ----------------
extern "C" void kernel_launch(void* const* d_in, const int* in_sizes, int n_in,
                              void* d_out, int out_size) {
    const float* x  = (const float*)d_in[0];
    const float* W1 = (const float*)d_in[1];
    const float* b1 = (const float*)d_in[2];
    const float* W2 = (const float*)d_in[3];
    const float* b2 = (const float*)d_in[4];
    const void*  ei = d_in[5];
    const int E = in_sizes[5] / 2;
    float* out = (float*)d_out;

    void *p_h1, *p_acc1, *p_h2, *p_acc2, *p_deg;
    cudaGetSymbolAddress(&p_h1,   g_h1);
    cudaGetSymbolAddress(&p_acc1, g_acc1);
    cudaGetSymbolAddress(&p_h2,   g_h2);
    cudaGetSymbolAddress(&p_acc2, g_acc2);
    cudaGetSymbolAddress(&p_deg,  g_deg);

    cudaMemsetAsync(p_acc1, 0, sizeof(float) * (size_t)N_NODES * C1);
    cudaMemsetAsync(p_acc2, 0, sizeof(float) * (size_t)N_NODES * C2);
    cudaMemsetAsync(p_deg,  0, sizeof(int) * N_NODES);

    detect_kernel<<<1, 32>>>((const int*)ei);
    deg_kernel<<<(E + 255) / 256, 256>>>(ei, E);
    dinv_kernel<<<(N_NODES + 255) / 256, 256>>>();

    // GEMM1: h1 = x @ W1   [100000,128] x [128,128]
    {
        dim3 grid(1, (N_NODES + 127) / 128);
        sgemm<128, 128, 8, 8, 8><<<grid, 256>>>(N_NODES, C1, C1, x, W1, (float*)p_h1);
    }

    // layer-1 aggregation
    {
        long long threads = (long long)E * 32;
        int blocks = (int)((threads + 255) / 256);
        scatter128<<<blocks, 256>>>((const float*)p_h1, ei, E, (float*)p_acc1);
    }
    epi1_kernel<<<(N_NODES * (C1 / 4) + 255) / 256, 256>>>(b1);

    // GEMM2: h2 = h1 @ W2   [100000,128] x [128,64]
    {
        dim3 grid(1, (N_NODES + 127) / 128);
        sgemm<128, 64, 8, 8, 8><<<grid, 128>>>(N_NODES, C2, C1, (const float*)p_h1, W2, (float*)p_h2);
    }

    // layer-2 aggregation
    {
        int warps = (E + 1) / 2;
        long long threads = (long long)warps * 32;
        int blocks = (int)((threads + 255) / 256);
        scatter64<<<blocks, 256>>>((const float*)p_h2, ei, E, (float*)p_acc2);
    }
    epi2_kernel<<<(N_NODES * (C2 / 4) + 255) / 256, 256>>>(b2, out);
}

// round 6
// speedup vs baseline: 1.5531x; 1.5531x over previous
#include <cuda_runtime.h>
#include <cstdint>

#define N_NODES 100000
#define C1 128
#define C2 64
#define E_MAX 1600000
#define SCAN_BLK 1024
#define SCAN_NB ((N_NODES + SCAN_BLK - 1) / SCAN_BLK)   // 98

// ---------------- scratch (static device globals; no allocation) ----------------
__device__ float g_h1 [(size_t)N_NODES * C1];   // x@W1
__device__ float g_h1b[(size_t)N_NODES * C1];   // relu(gcn1) output
__device__ float g_h2 [(size_t)N_NODES * C2];   // h1b@W2
__device__ float g_dinv[N_NODES];
__device__ int   g_deg [N_NODES];
__device__ int   g_row [N_NODES + 1];           // CSR row offsets (by dst)
__device__ int   g_csr [E_MAX];                 // src index per edge, grouped by dst
__device__ int   g_cursor[N_NODES];
__device__ int   g_bsum[SCAN_NB];
__device__ int   g_is64;

// ---------------- edge dtype detection ----------------
// int64 values < 100000 => every high 32-bit word is 0.
// int32 => odd int32 positions are random node ids; P(all 1024 zero) ~ 0.
__global__ void detect_kernel(const int* __restrict__ ei) {
    if (blockIdx.x == 0 && threadIdx.x == 0) {
        int any = 0;
        for (int i = 0; i < 1024; i++) any |= ei[2 * i + 1];
        g_is64 = (any == 0) ? 1 : 0;
    }
}

__device__ __forceinline__ int load_idx(const void* ei, long long pos) {
    if (g_is64) return (int)((const long long*)ei)[pos];
    return ((const int*)ei)[pos];
}

// ---------------- degree + dinv ----------------
__global__ void deg_kernel(const void* __restrict__ ei, int E) {
    int t = blockIdx.x * blockDim.x + threadIdx.x;
    if (t >= E) return;
    int d = load_idx(ei, (long long)E + t);
    atomicAdd(&g_deg[d], 1);
}

__global__ void dinv_kernel() {
    int t = blockIdx.x * blockDim.x + threadIdx.x;
    if (t < N_NODES) g_dinv[t] = rsqrtf((float)g_deg[t] + 1.0f);
}

// ---------------- prefix scan over deg -> g_row ----------------
__global__ void scan_block_kernel() {
    __shared__ int sm[SCAN_BLK];
    int tid = threadIdx.x;
    int i = blockIdx.x * SCAN_BLK + tid;
    int v = (i < N_NODES) ? g_deg[i] : 0;
    sm[tid] = v;
    __syncthreads();
    #pragma unroll
    for (int off = 1; off < SCAN_BLK; off <<= 1) {
        int t = (tid >= off) ? sm[tid - off] : 0;
        __syncthreads();
        sm[tid] += t;
        __syncthreads();
    }
    if (i < N_NODES) g_row[i] = sm[tid] - v;        // exclusive
    if (tid == SCAN_BLK - 1) g_bsum[blockIdx.x] = sm[tid];
}

__global__ void scan_top_kernel() {
    __shared__ int sm[128];
    int tid = threadIdx.x;
    int v = (tid < SCAN_NB) ? g_bsum[tid] : 0;
    sm[tid] = v;
    __syncthreads();
    #pragma unroll
    for (int off = 1; off < 128; off <<= 1) {
        int t = (tid >= off) ? sm[tid - off] : 0;
        __syncthreads();
        sm[tid] += t;
        __syncthreads();
    }
    if (tid < SCAN_NB) g_bsum[tid] = sm[tid] - v;   // exclusive block offsets
    if (tid == 127) g_row[N_NODES] = sm[127];       // = E
}

__global__ void scan_add_kernel() {
    int i = blockIdx.x * blockDim.x + threadIdx.x;
    if (i < N_NODES) g_row[i] += g_bsum[i >> 10];
}

// ---------------- CSR fill ----------------
__global__ void fill_kernel(const void* __restrict__ ei, int E) {
    int t = blockIdx.x * blockDim.x + threadIdx.x;
    if (t >= E) return;
    int s = load_idx(ei, t);
    int d = load_idx(ei, (long long)E + t);
    int pos = g_row[d] + atomicAdd(&g_cursor[d], 1);
    g_csr[pos] = s;
}

// ---------------- register-blocked SGEMM: C[M,N] = A[M,K] * B[K,N] ----------------
template <int BM, int BN, int BK, int TM, int TN>
__global__ void sgemm(int M, int N, int K,
                      const float* __restrict__ A,
                      const float* __restrict__ B,
                      float* __restrict__ C) {
    const int numThreads = (BM / TM) * (BN / TN);
    const int cRow = blockIdx.y;
    const int cCol = blockIdx.x;

    __shared__ float As[BK][BM];
    __shared__ float Bs[BK][BN];

    const int threadCol = threadIdx.x % (BN / TN);
    const int threadRow = threadIdx.x / (BN / TN);

    A += (size_t)cRow * BM * K;
    B += cCol * BN;
    C += (size_t)cRow * BM * N + cCol * BN;
    const int rowBase = cRow * BM;

    const int innerRowA = threadIdx.x / (BK / 4);
    const int innerColA = threadIdx.x % (BK / 4);
    const int strideA   = numThreads / (BK / 4);
    const int innerRowB = threadIdx.x / (BN / 4);
    const int innerColB = threadIdx.x % (BN / 4);
    const int strideB   = numThreads / (BN / 4);

    float regM[TM], regN[TN];
    float acc[TM][TN];
    #pragma unroll
    for (int i = 0; i < TM; i++)
        #pragma unroll
        for (int j = 0; j < TN; j++) acc[i][j] = 0.f;

    for (int k0 = 0; k0 < K; k0 += BK) {
        #pragma unroll
        for (int r = innerRowA; r < BM; r += strideA) {
            float4 t = make_float4(0.f, 0.f, 0.f, 0.f);
            if (rowBase + r < M)
                t = *(const float4*)(A + (size_t)r * K + innerColA * 4);
            As[innerColA * 4 + 0][r] = t.x;
            As[innerColA * 4 + 1][r] = t.y;
            As[innerColA * 4 + 2][r] = t.z;
            As[innerColA * 4 + 3][r] = t.w;
        }
        #pragma unroll
        for (int r = innerRowB; r < BK; r += strideB) {
            float4 t = *(const float4*)(B + (size_t)r * N + innerColB * 4);
            *(float4*)(&Bs[r][innerColB * 4]) = t;
        }
        __syncthreads();
        A += BK;
        B += (size_t)BK * N;

        #pragma unroll
        for (int k = 0; k < BK; k++) {
            #pragma unroll
            for (int i = 0; i < TM; i++) regM[i] = As[k][threadRow * TM + i];
            #pragma unroll
            for (int j = 0; j < TN; j++) regN[j] = Bs[k][threadCol * TN + j];
            #pragma unroll
            for (int i = 0; i < TM; i++)
                #pragma unroll
                for (int j = 0; j < TN; j++) acc[i][j] += regM[i] * regN[j];
        }
        __syncthreads();
    }

    #pragma unroll
    for (int i = 0; i < TM; i++) {
        int r = threadRow * TM + i;
        if (rowBase + r >= M) continue;
        #pragma unroll
        for (int j = 0; j < TN; j += 4) {
            float4 t;
            t.x = acc[i][j + 0]; t.y = acc[i][j + 1];
            t.z = acc[i][j + 2]; t.w = acc[i][j + 3];
            *(float4*)(&C[(size_t)r * N + threadCol * TN + j]) = t;
        }
    }
}

// ---------------- layer-1 aggregation (CSR, warp per node, fused epilogue) ----------------
// out[n] = relu( dinv[n] * sum_{s->n} h[s]*dinv[s] + dinv[n]^2 * h[n] + b1 )
__global__ void agg1_kernel(const float* __restrict__ h, const float* __restrict__ b1,
                            float* __restrict__ outp) {
    int warp = (int)(((long long)blockIdx.x * blockDim.x + threadIdx.x) >> 5);
    int lane = threadIdx.x & 31;
    if (warp >= N_NODES) return;
    int beg = __ldg(&g_row[warp]);
    int end = __ldg(&g_row[warp + 1]);

    float4 acc = make_float4(0.f, 0.f, 0.f, 0.f);
    int i = beg;
    for (; i + 2 <= end; i += 2) {
        int s0 = __ldg(&g_csr[i]);
        int s1 = __ldg(&g_csr[i + 1]);
        float n0 = __ldg(&g_dinv[s0]);
        float n1 = __ldg(&g_dinv[s1]);
        float4 v0 = __ldg((const float4*)h + (size_t)s0 * (C1 / 4) + lane);
        float4 v1 = __ldg((const float4*)h + (size_t)s1 * (C1 / 4) + lane);
        acc.x = fmaf(v0.x, n0, acc.x); acc.y = fmaf(v0.y, n0, acc.y);
        acc.z = fmaf(v0.z, n0, acc.z); acc.w = fmaf(v0.w, n0, acc.w);
        acc.x = fmaf(v1.x, n1, acc.x); acc.y = fmaf(v1.y, n1, acc.y);
        acc.z = fmaf(v1.z, n1, acc.z); acc.w = fmaf(v1.w, n1, acc.w);
    }
    if (i < end) {
        int s0 = __ldg(&g_csr[i]);
        float n0 = __ldg(&g_dinv[s0]);
        float4 v0 = __ldg((const float4*)h + (size_t)s0 * (C1 / 4) + lane);
        acc.x = fmaf(v0.x, n0, acc.x); acc.y = fmaf(v0.y, n0, acc.y);
        acc.z = fmaf(v0.z, n0, acc.z); acc.w = fmaf(v0.w, n0, acc.w);
    }

    float di  = __ldg(&g_dinv[warp]);
    float di2 = di * di;
    float4 hh = __ldg((const float4*)h + (size_t)warp * (C1 / 4) + lane);
    float4 b  = __ldg((const float4*)b1 + lane);
    float4 o;
    o.x = fmaxf(fmaf(di, acc.x, fmaf(di2, hh.x, b.x)), 0.f);
    o.y = fmaxf(fmaf(di, acc.y, fmaf(di2, hh.y, b.y)), 0.f);
    o.z = fmaxf(fmaf(di, acc.z, fmaf(di2, hh.z, b.z)), 0.f);
    o.w = fmaxf(fmaf(di, acc.w, fmaf(di2, hh.w, b.w)), 0.f);
    ((float4*)outp)[(size_t)warp * (C1 / 4) + lane] = o;
}

// ---------------- layer-2 aggregation (CSR, half-warp per node, fused epilogue) ----------------
__global__ void agg2_kernel(const float* __restrict__ h, const float* __restrict__ b2,
                            float* __restrict__ outp) {
    int warp = (int)(((long long)blockIdx.x * blockDim.x + threadIdx.x) >> 5);
    int lane = threadIdx.x & 31;
    int node = warp * 2 + (lane >> 4);
    int sub  = lane & 15;
    if (node >= N_NODES) return;
    int beg = __ldg(&g_row[node]);
    int end = __ldg(&g_row[node + 1]);

    float4 acc = make_float4(0.f, 0.f, 0.f, 0.f);
    int i = beg;
    for (; i + 2 <= end; i += 2) {
        int s0 = __ldg(&g_csr[i]);
        int s1 = __ldg(&g_csr[i + 1]);
        float n0 = __ldg(&g_dinv[s0]);
        float n1 = __ldg(&g_dinv[s1]);
        float4 v0 = __ldg((const float4*)h + (size_t)s0 * (C2 / 4) + sub);
        float4 v1 = __ldg((const float4*)h + (size_t)s1 * (C2 / 4) + sub);
        acc.x = fmaf(v0.x, n0, acc.x); acc.y = fmaf(v0.y, n0, acc.y);
        acc.z = fmaf(v0.z, n0, acc.z); acc.w = fmaf(v0.w, n0, acc.w);
        acc.x = fmaf(v1.x, n1, acc.x); acc.y = fmaf(v1.y, n1, acc.y);
        acc.z = fmaf(v1.z, n1, acc.z); acc.w = fmaf(v1.w, n1, acc.w);
    }
    if (i < end) {
        int s0 = __ldg(&g_csr[i]);
        float n0 = __ldg(&g_dinv[s0]);
        float4 v0 = __ldg((const float4*)h + (size_t)s0 * (C2 / 4) + sub);
        acc.x = fmaf(v0.x, n0, acc.x); acc.y = fmaf(v0.y, n0, acc.y);
        acc.z = fmaf(v0.z, n0, acc.z); acc.w = fmaf(v0.w, n0, acc.w);
    }

    float di  = __ldg(&g_dinv[node]);
    float di2 = di * di;
    float4 hh = __ldg((const float4*)h + (size_t)node * (C2 / 4) + sub);
    float4 b  = __ldg((const float4*)b2 + sub);
    float4 o;
    o.x = fmaf(di, acc.x, fmaf(di2, hh.x, b.x));
    o.y = fmaf(di, acc.y, fmaf(di2, hh.y, b.y));
    o.z = fmaf(di, acc.z, fmaf(di2, hh.z, b.z));
    o.w = fmaf(di, acc.w, fmaf(di2, hh.w, b.w));
    ((float4*)outp)[(size_t)node * (C2 / 4) + sub] = o;
}

// ---------------- launch ----------------
extern "C" void kernel_launch(void* const* d_in, const int* in_sizes, int n_in,
                              void* d_out, int out_size) {
    const float* x  = (const float*)d_in[0];
    const float* W1 = (const float*)d_in[1];
    const float* b1 = (const float*)d_in[2];
    const float* W2 = (const float*)d_in[3];
    const float* b2 = (const float*)d_in[4];
    const void*  ei = d_in[5];
    const int E = in_sizes[5] / 2;
    float* out = (float*)d_out;

    void *p_h1, *p_h1b, *p_h2, *p_deg, *p_cur;
    cudaGetSymbolAddress(&p_h1,  g_h1);
    cudaGetSymbolAddress(&p_h1b, g_h1b);
    cudaGetSymbolAddress(&p_h2,  g_h2);
    cudaGetSymbolAddress(&p_deg, g_deg);
    cudaGetSymbolAddress(&p_cur, g_cursor);

    cudaMemsetAsync(p_deg, 0, sizeof(int) * N_NODES);
    cudaMemsetAsync(p_cur, 0, sizeof(int) * N_NODES);

    detect_kernel<<<1, 32>>>((const int*)ei);
    deg_kernel<<<(E + 255) / 256, 256>>>(ei, E);
    dinv_kernel<<<(N_NODES + 255) / 256, 256>>>();

    // CSR build
    scan_block_kernel<<<SCAN_NB, SCAN_BLK>>>();
    scan_top_kernel<<<1, 128>>>();
    scan_add_kernel<<<(N_NODES + 255) / 256, 256>>>();
    fill_kernel<<<(E + 255) / 256, 256>>>(ei, E);

    // GEMM1: h1 = x @ W1   [100000,128] x [128,128]
    {
        dim3 grid(1, (N_NODES + 127) / 128);
        sgemm<128, 128, 8, 8, 8><<<grid, 256>>>(N_NODES, C1, C1, x, W1, (float*)p_h1);
    }

    // layer-1 aggregation + epilogue (warp per node)
    {
        long long threads = (long long)N_NODES * 32;
        int blocks = (int)((threads + 255) / 256);
        agg1_kernel<<<blocks, 256>>>((const float*)p_h1, b1, (float*)p_h1b);
    }

    // GEMM2: h2 = h1b @ W2   [100000,128] x [128,64]
    {
        dim3 grid(1, (N_NODES + 127) / 128);
        sgemm<128, 64, 8, 8, 8><<<grid, 128>>>(N_NODES, C2, C1, (const float*)p_h1b, W2, (float*)p_h2);
    }

    // layer-2 aggregation + epilogue (half-warp per node) -> final output
    {
        long long threads = (long long)((N_NODES + 1) / 2) * 32;
        int blocks = (int)((threads + 255) / 256);
        agg2_kernel<<<blocks, 256>>>((const float*)p_h2, b2, out);
    }
}